// round 1
// baseline (speedup 1.0000x reference)
#include <cuda_runtime.h>
#include <cstdint>

// Problem constants (fixed by setup_inputs)
#define NN    100000
#define EMAX  3200000
#define CIN   128
#define CHID  16
#define COUT  128

// ---------------- static scratch (no allocations allowed) ----------------
__device__ int   g_is64;
__device__ int   g_deg [NN];
__device__ float g_dinv[NN];
__device__ float g_h   [NN * CHID];   // gather source (pre-scaled by dinv[src])
__device__ float g_acc [NN * CHID];   // scatter accumulator (init = self-loop term)
__device__ int2  g_edges[EMAX];       // packed (src,dst) int32

// ---------------- helpers ----------------
__device__ __forceinline__ void red_add_v4(float* p, float4 v) {
    asm volatile("red.global.add.v4.f32 [%0], {%1,%2,%3,%4};"
                 :: "l"(p), "f"(v.x), "f"(v.y), "f"(v.z), "f"(v.w) : "memory");
}

// ---------------- dtype detection for edge_index (int64 vs int32) ----------------
// Values are node ids < 100000 < 2^31. If stored as little-endian int64, every
// odd 32-bit word of the first 64 entries is 0. For genuine random int32 data the
// odds of that are ~0.
__global__ void detect_kernel(const unsigned int* __restrict__ e) {
    if (blockIdx.x == 0 && threadIdx.x == 0) {
        int is64 = 1;
        #pragma unroll
        for (int i = 1; i < 128; i += 2)
            if (e[i] != 0u) is64 = 0;
        g_is64 = is64;
    }
}

__global__ void initdeg_kernel() {
    int i = blockIdx.x * blockDim.x + threadIdx.x;
    if (i < NN) g_deg[i] = 1;   // self-loop
}

// Pack edges to int2 (handles either index dtype) and count in-degrees.
__global__ void prep_kernel(const void* __restrict__ eidx, int E) {
    int i = blockIdx.x * blockDim.x + threadIdx.x;
    if (i >= E || i >= EMAX) return;
    int s, d;
    if (g_is64) {
        const long long* p = (const long long*)eidx;
        s = (int)p[i];
        d = (int)p[(size_t)E + i];
    } else {
        const int* p = (const int*)eidx;
        s = p[i];
        d = p[(size_t)E + i];
    }
    g_edges[i] = make_int2(s, d);
    atomicAdd(&g_deg[d], 1);
}

__global__ void dinv_kernel() {
    int i = blockIdx.x * blockDim.x + threadIdx.x;
    if (i < NN) g_dinv[i] = rsqrtf((float)g_deg[i]);
}

// h1pre[n,f] = (x[n,:] @ W1[:,f]) * dinv[n]; also initializes accumulator.
// 256 threads: f = tid&15 (feature), nl = tid>>4 (node lane); 64 nodes/block.
__global__ void gemm1_kernel(const float* __restrict__ x, const float* __restrict__ W1) {
    __shared__ float w[CIN * CHID];
    for (int i = threadIdx.x; i < CIN * CHID; i += 256) w[i] = W1[i];
    __syncthreads();
    int f  = threadIdx.x & 15;
    int nl = threadIdx.x >> 4;
    #pragma unroll
    for (int it = 0; it < 4; ++it) {
        int node = blockIdx.x * 64 + it * 16 + nl;
        if (node >= NN) return;
        const float* xr = x + (size_t)node * CIN;
        float acc = 0.f;
        #pragma unroll
        for (int k = 0; k < CIN; ++k)
            acc = fmaf(xr[k], w[k * CHID + f], acc);
        float v = acc * g_dinv[node];
        g_h  [node * CHID + f] = v;
        g_acc[node * CHID + f] = v;
    }
}

// Pure scatter-add: acc[dst] += h[src], 16 floats/edge via 4x red.v4.
__global__ void scatter_kernel(int E) {
    int i = blockIdx.x * blockDim.x + threadIdx.x;
    if (i >= E) return;
    int2 e = g_edges[i];
    const float4* s = (const float4*)(g_h + (size_t)e.x * CHID);
    float4 v0 = s[0], v1 = s[1], v2 = s[2], v3 = s[3];
    float* dp = g_acc + (size_t)e.y * CHID;
    red_add_v4(dp + 0,  v0);
    red_add_v4(dp + 4,  v1);
    red_add_v4(dp + 8,  v2);
    red_add_v4(dp + 12, v3);
}

// out1 = relu(dinv*acc + b1); rpre = out1*dinv -> becomes both gather source and
// the new accumulator init (self-loop term) for layer 2. float4 over NN*4 threads.
__global__ void fin1_kernel(const float* __restrict__ b1) {
    int i = blockIdx.x * blockDim.x + threadIdx.x;
    if (i >= NN * 4) return;
    int node = i >> 2, q = i & 3;
    float  dv = g_dinv[node];
    float4 a  = ((const float4*)g_acc)[i];
    float4 bb = ((const float4*)b1)[q];
    float4 v;
    v.x = fmaxf(fmaf(a.x, dv, bb.x), 0.f) * dv;
    v.y = fmaxf(fmaf(a.y, dv, bb.y), 0.f) * dv;
    v.z = fmaxf(fmaf(a.z, dv, bb.z), 0.f) * dv;
    v.w = fmaxf(fmaf(a.w, dv, bb.w), 0.f) * dv;
    ((float4*)g_h)[i]   = v;
    ((float4*)g_acc)[i] = v;
}

// out[n,f] = b2[f] + dinv[n] * (acc2[n,:] @ W2[:,f])
// 256 threads: f = tid&127, nl = tid>>7; 64 nodes/block (32 iters of 2).
__global__ void gemm2_kernel(const float* __restrict__ W2, const float* __restrict__ b2,
                             float* __restrict__ out) {
    __shared__ float w[CHID * COUT];
    __shared__ float bs[COUT];
    for (int i = threadIdx.x; i < CHID * COUT; i += 256) w[i] = W2[i];
    if (threadIdx.x < COUT) bs[threadIdx.x] = b2[threadIdx.x];
    __syncthreads();
    int f  = threadIdx.x & 127;
    int nl = threadIdx.x >> 7;
    for (int it = 0; it < 32; ++it) {
        int node = blockIdx.x * 64 + it * 2 + nl;
        if (node >= NN) return;
        const float* t = g_acc + (size_t)node * CHID;
        float dv = g_dinv[node];
        float s = 0.f;
        #pragma unroll
        for (int k = 0; k < CHID; ++k)
            s = fmaf(t[k], w[k * COUT + f], s);
        out[(size_t)node * COUT + f] = fmaf(s, dv, bs[f]);
    }
}

// ---------------- launch ----------------
extern "C" void kernel_launch(void* const* d_in, const int* in_sizes, int n_in,
                              void* d_out, int out_size) {
    const float* x    = (const float*)d_in[0];
    const void*  eidx = d_in[1];
    const float* W1   = (const float*)d_in[2];
    const float* b1   = (const float*)d_in[3];
    const float* W2   = (const float*)d_in[4];
    const float* b2   = (const float*)d_in[5];
    float*       out  = (float*)d_out;
    int E = in_sizes[1] / 2;

    detect_kernel<<<1, 32>>>((const unsigned int*)eidx);
    initdeg_kernel<<<(NN + 255) / 256, 256>>>();
    prep_kernel<<<(E + 255) / 256, 256>>>(eidx, E);
    dinv_kernel<<<(NN + 255) / 256, 256>>>();

    gemm1_kernel<<<(NN + 63) / 64, 256>>>(x, W1);
    scatter_kernel<<<(E + 255) / 256, 256>>>(E);
    fin1_kernel<<<(NN * 4 + 255) / 256, 256>>>(b1);
    scatter_kernel<<<(E + 255) / 256, 256>>>(E);
    gemm2_kernel<<<(NN + 63) / 64, 256>>>(W2, b2, out);
}

// round 2
// speedup vs baseline: 1.3070x; 1.3070x over previous
#include <cuda_runtime.h>
#include <cstdint>

// Problem constants (fixed by setup_inputs)
#define NN    100000
#define EMAX  3200000
#define CIN   128
#define CHID  16
#define COUT  128

#define SCAN_B 512
#define NB ((NN + SCAN_B - 1) / SCAN_B)   // 196

// ---------------- static scratch (no allocations allowed) ----------------
__device__ int   g_is64;
__device__ int   g_deg   [NN];         // in-degree (excl. self-loop)
__device__ int   g_cursor[NN];
__device__ int   g_offs  [NN + 1];     // CSR row offsets (by dst)
__device__ int   g_bsum  [NB];
__device__ int   g_bsumx [NB];
__device__ float g_dinv  [NN];
__device__ float g_h     [NN * CHID];  // gather source (pre-scaled by dinv[src])
__device__ float g_acc   [NN * CHID];  // aggregation result
__device__ int2  g_edges [EMAX];       // packed (src,dst) int32
__device__ int   g_csr   [EMAX];       // src ids grouped by dst

// ---------------- dtype detection for edge_index (int64 vs int32) ----------------
__global__ void detect_kernel(const unsigned int* __restrict__ e) {
    if (threadIdx.x == 0) {
        int is64 = 1;
        #pragma unroll
        for (int i = 1; i < 128; i += 2)
            if (e[i] != 0u) is64 = 0;
        g_is64 = is64;
    }
}

__global__ void zero_kernel() {
    int i = blockIdx.x * blockDim.x + threadIdx.x;
    if (i < NN) { g_deg[i] = 0; g_cursor[i] = 0; }
}

// Pack edges to int2 (either index dtype) and count in-degrees.
__global__ void prep_kernel(const void* __restrict__ eidx, int E) {
    int i = blockIdx.x * blockDim.x + threadIdx.x;
    if (i >= E) return;
    int s, d;
    if (g_is64) {
        const long long* p = (const long long*)eidx;
        s = (int)p[i];
        d = (int)p[(size_t)E + i];
    } else {
        const int* p = (const int*)eidx;
        s = p[i];
        d = p[(size_t)E + i];
    }
    g_edges[i] = make_int2(s, d);
    atomicAdd(&g_deg[d], 1);
}

// ---- 3-phase exclusive scan of g_deg into g_offs ----
__global__ void scanA_kernel() {
    __shared__ int sh[SCAN_B];
    int i = blockIdx.x * SCAN_B + threadIdx.x;
    int v = (i < NN) ? g_deg[i] : 0;
    sh[threadIdx.x] = v;
    __syncthreads();
    for (int off = 1; off < SCAN_B; off <<= 1) {
        int t = (threadIdx.x >= off) ? sh[threadIdx.x - off] : 0;
        __syncthreads();
        sh[threadIdx.x] += t;
        __syncthreads();
    }
    if (i < NN) g_offs[i] = sh[threadIdx.x] - v;            // block-local exclusive
    if (threadIdx.x == SCAN_B - 1) g_bsum[blockIdx.x] = sh[SCAN_B - 1];
}

__global__ void scanB_kernel() {
    __shared__ int sh[256];
    int v = (threadIdx.x < NB) ? g_bsum[threadIdx.x] : 0;
    sh[threadIdx.x] = v;
    __syncthreads();
    for (int off = 1; off < 256; off <<= 1) {
        int t = (threadIdx.x >= off) ? sh[threadIdx.x - off] : 0;
        __syncthreads();
        sh[threadIdx.x] += t;
        __syncthreads();
    }
    if (threadIdx.x < NB) g_bsumx[threadIdx.x] = sh[threadIdx.x] - v;
}

__global__ void scanC_kernel(int E) {
    int i = blockIdx.x * blockDim.x + threadIdx.x;
    if (i < NN) g_offs[i] += g_bsumx[i / SCAN_B];
    if (i == 0) g_offs[NN] = E;
    if (i < NN) g_dinv[i] = rsqrtf((float)(g_deg[i] + 1));   // +1 self-loop
}

// Bucket src ids by dst.
__global__ void fill_kernel(int E) {
    int i = blockIdx.x * blockDim.x + threadIdx.x;
    if (i >= E) return;
    int2 e = g_edges[i];
    int pos = g_offs[e.y] + atomicAdd(&g_cursor[e.y], 1);
    g_csr[pos] = e.x;
}

// h1pre[n,f] = (x[n,:] @ W1[:,f]) * dinv[n]
__global__ void gemm1_kernel(const float* __restrict__ x, const float* __restrict__ W1) {
    __shared__ float w[CIN * CHID];
    for (int i = threadIdx.x; i < CIN * CHID; i += 256) w[i] = W1[i];
    __syncthreads();
    int f  = threadIdx.x & 15;
    int nl = threadIdx.x >> 4;
    #pragma unroll
    for (int it = 0; it < 4; ++it) {
        int node = blockIdx.x * 64 + it * 16 + nl;
        if (node >= NN) return;
        const float* xr = x + (size_t)node * CIN;
        float acc = 0.f;
        #pragma unroll
        for (int k = 0; k < CIN; ++k)
            acc = fmaf(xr[k], w[k * CHID + f], acc);
        g_h[node * CHID + f] = acc * g_dinv[node];
    }
}

// Atomic-free aggregation: one half-warp per dst, lane = feature.
// acc[dst,f] = h[dst,f] (self-loop) + sum over in-edges of h[src,f].
__global__ void agg_kernel() {
    int tid  = blockIdx.x * blockDim.x + threadIdx.x;
    int dst  = tid >> 4;          // 16 threads per dst
    int f    = tid & 15;
    if (dst >= NN) return;
    int start = g_offs[dst];
    int end   = g_offs[dst + 1];
    float acc = g_h[dst * CHID + f];          // self-loop term
    int j = start;
    for (; j + 4 <= end; j += 4) {
        int s0 = g_csr[j], s1 = g_csr[j + 1], s2 = g_csr[j + 2], s3 = g_csr[j + 3];
        float a0 = __ldg(&g_h[s0 * CHID + f]);
        float a1 = __ldg(&g_h[s1 * CHID + f]);
        float a2 = __ldg(&g_h[s2 * CHID + f]);
        float a3 = __ldg(&g_h[s3 * CHID + f]);
        acc += (a0 + a1) + (a2 + a3);
    }
    for (; j < end; ++j)
        acc += __ldg(&g_h[g_csr[j] * CHID + f]);
    g_acc[dst * CHID + f] = acc;
}

// h2pre = relu(dinv*acc + b1) * dinv  -> new gather source for layer 2.
__global__ void fin1_kernel(const float* __restrict__ b1) {
    int i = blockIdx.x * blockDim.x + threadIdx.x;
    if (i >= NN * 4) return;
    int node = i >> 2, q = i & 3;
    float  dv = g_dinv[node];
    float4 a  = ((const float4*)g_acc)[i];
    float4 bb = ((const float4*)b1)[q];
    float4 v;
    v.x = fmaxf(fmaf(a.x, dv, bb.x), 0.f) * dv;
    v.y = fmaxf(fmaf(a.y, dv, bb.y), 0.f) * dv;
    v.z = fmaxf(fmaf(a.z, dv, bb.z), 0.f) * dv;
    v.w = fmaxf(fmaf(a.w, dv, bb.w), 0.f) * dv;
    ((float4*)g_h)[i] = v;
}

// out[n,f] = b2[f] + dinv[n] * (acc2[n,:] @ W2[:,f])
__global__ void gemm2_kernel(const float* __restrict__ W2, const float* __restrict__ b2,
                             float* __restrict__ out) {
    __shared__ float w[CHID * COUT];
    __shared__ float bs[COUT];
    for (int i = threadIdx.x; i < CHID * COUT; i += 256) w[i] = W2[i];
    if (threadIdx.x < COUT) bs[threadIdx.x] = b2[threadIdx.x];
    __syncthreads();
    int f  = threadIdx.x & 127;
    int nl = threadIdx.x >> 7;
    for (int it = 0; it < 32; ++it) {
        int node = blockIdx.x * 64 + it * 2 + nl;
        if (node >= NN) return;
        const float* t = g_acc + (size_t)node * CHID;
        float dv = g_dinv[node];
        float s = 0.f;
        #pragma unroll
        for (int k = 0; k < CHID; ++k)
            s = fmaf(t[k], w[k * COUT + f], s);
        out[(size_t)node * COUT + f] = fmaf(s, dv, bs[f]);
    }
}

// ---------------- launch ----------------
extern "C" void kernel_launch(void* const* d_in, const int* in_sizes, int n_in,
                              void* d_out, int out_size) {
    const float* x    = (const float*)d_in[0];
    const void*  eidx = d_in[1];
    const float* W1   = (const float*)d_in[2];
    const float* b1   = (const float*)d_in[3];
    const float* W2   = (const float*)d_in[4];
    const float* b2   = (const float*)d_in[5];
    float*       out  = (float*)d_out;
    int E = in_sizes[1] / 2;

    detect_kernel<<<1, 32>>>((const unsigned int*)eidx);
    zero_kernel<<<(NN + 255) / 256, 256>>>();
    prep_kernel<<<(E + 255) / 256, 256>>>(eidx, E);
    scanA_kernel<<<NB, SCAN_B>>>();
    scanB_kernel<<<1, 256>>>();
    scanC_kernel<<<(NN + 255) / 256, 256>>>(E);
    fill_kernel<<<(E + 255) / 256, 256>>>(E);

    gemm1_kernel<<<(NN + 63) / 64, 256>>>(x, W1);
    agg_kernel<<<(NN * 16 + 255) / 256, 256>>>();
    fin1_kernel<<<(NN * 4 + 255) / 256, 256>>>(b1);
    agg_kernel<<<(NN * 16 + 255) / 256, 256>>>();
    gemm2_kernel<<<(NN + 63) / 64, 256>>>(W2, b2, out);
}

// round 3
// speedup vs baseline: 2.0562x; 1.5732x over previous
#include <cuda_runtime.h>
#include <cuda_fp16.h>
#include <cstdint>

// Problem constants (fixed by setup_inputs)
#define NN    100000
#define EMAX  3200000
#define CIN   128
#define CHID  16
#define COUT  128
#define PADMAX (EMAX + 3 * NN + 16)     // CSR rows padded to multiple of 4

#define SCAN_B 512
#define NB ((NN + SCAN_B - 1) / SCAN_B)   // 196

// ---------------- static scratch (no allocations allowed) ----------------
__device__ int    g_is64;
__device__ int    g_deg   [NN];          // real in-degree (excl. self-loop)
__device__ int    g_cursor[NN];
__device__ int    g_offs  [NN + 1];      // padded CSR row offsets (all %4==0)
__device__ int    g_bsum  [NB];
__device__ int    g_bsumx [NB];
__device__ float  g_dinv  [NN];
__device__ __half g_h16a  [(NN + 1) * CHID];  // layer-1 gather source (row NN = zeros)
__device__ __half g_h16b  [(NN + 1) * CHID];  // layer-2 gather source (row NN = zeros)
__device__ float  g_acc   [NN * CHID];        // layer-2 aggregation result (fp32)
__device__ int2   g_edges [EMAX];
__device__ int    g_csr   [PADMAX];           // src ids grouped by dst, pad = NN

// ---------------- init: detect dtype, zero counters, dummy-fill csr ----------------
__global__ void init_kernel(const unsigned int* __restrict__ e) {
    int i = blockIdx.x * blockDim.x + threadIdx.x;
    if (i == 0) {
        int is64 = 1;
        #pragma unroll
        for (int k = 1; k < 128; k += 2)
            if (e[k] != 0u) is64 = 0;
        g_is64 = is64;
    }
    if (i < NN) { g_deg[i] = 0; g_cursor[i] = 0; }
    if (i < PADMAX / 4)
        ((int4*)g_csr)[i] = make_int4(NN, NN, NN, NN);
    if (i < CHID) { g_h16a[NN * CHID + i] = __float2half(0.f);
                    g_h16b[NN * CHID + i] = __float2half(0.f); }
}

// Pack edges to int2 (either index dtype) and count in-degrees.
__global__ void prep_kernel(const void* __restrict__ eidx, int E) {
    int i = blockIdx.x * blockDim.x + threadIdx.x;
    if (i >= E) return;
    int s, d;
    if (g_is64) {
        const long long* p = (const long long*)eidx;
        s = (int)p[i];
        d = (int)p[(size_t)E + i];
    } else {
        const int* p = (const int*)eidx;
        s = p[i];
        d = p[(size_t)E + i];
    }
    g_edges[i] = make_int2(s, d);
    atomicAdd(&g_deg[d], 1);
}

// ---- 3-phase exclusive scan of PADDED degrees into g_offs ----
__global__ void scanA_kernel() {
    __shared__ int sh[SCAN_B];
    int i = blockIdx.x * SCAN_B + threadIdx.x;
    int v = (i < NN) ? ((g_deg[i] + 3) & ~3) : 0;
    sh[threadIdx.x] = v;
    __syncthreads();
    for (int off = 1; off < SCAN_B; off <<= 1) {
        int t = (threadIdx.x >= off) ? sh[threadIdx.x - off] : 0;
        __syncthreads();
        sh[threadIdx.x] += t;
        __syncthreads();
    }
    if (i < NN) g_offs[i] = sh[threadIdx.x] - v;
    if (threadIdx.x == SCAN_B - 1) g_bsum[blockIdx.x] = sh[SCAN_B - 1];
}

__global__ void scanB_kernel() {
    __shared__ int sh[256];
    int v = (threadIdx.x < NB) ? g_bsum[threadIdx.x] : 0;
    sh[threadIdx.x] = v;
    __syncthreads();
    for (int off = 1; off < 256; off <<= 1) {
        int t = (threadIdx.x >= off) ? sh[threadIdx.x - off] : 0;
        __syncthreads();
        sh[threadIdx.x] += t;
        __syncthreads();
    }
    if (threadIdx.x < NB) g_bsumx[threadIdx.x] = sh[threadIdx.x] - v;
    if (threadIdx.x == NB - 1) g_offs[NN] = sh[NB - 1];
}

__global__ void scanC_kernel() {
    int i = blockIdx.x * blockDim.x + threadIdx.x;
    if (i < NN) {
        g_offs[i] += g_bsumx[i / SCAN_B];
        g_dinv[i] = rsqrtf((float)(g_deg[i] + 1));   // +1 self-loop
    }
}

// Bucket src ids by dst (row starts 4-aligned; tail slots keep dummy NN).
__global__ void fill_kernel(int E) {
    int i = blockIdx.x * blockDim.x + threadIdx.x;
    if (i >= E) return;
    int2 e = g_edges[i];
    int pos = g_offs[e.y] + atomicAdd(&g_cursor[e.y], 1);
    g_csr[pos] = e.x;
}

// h16a[n,f] = fp16( (x[n,:] @ W1[:,f]) * dinv[n] )
// block: 64 nodes, 256 threads = 64 nodes x 4 feature-groups (4 feats each).
__global__ __launch_bounds__(256) void gemm1_kernel(const float4* __restrict__ x4,
                                                    const float4* __restrict__ W14) {
    __shared__ float4 shx[64 * 33];     // padded stride 33 f4 (132 floats)
    __shared__ float4 shw[128 * 4];     // shw[k*4 + fg] = W1[k][fg*4..fg*4+3]
    int t = threadIdx.x;
    for (int i = t; i < 512; i += 256) shw[i] = W14[i];
    int base = blockIdx.x * 2048;       // 64 rows * 32 f4
    #pragma unroll
    for (int i = 0; i < 8; ++i) {
        int idx = t + i * 256;
        int row = idx >> 5, col = idx & 31;
        shx[row * 33 + col] = (blockIdx.x * 64 + row < NN) ? x4[base + idx]
                                                           : make_float4(0.f, 0.f, 0.f, 0.f);
    }
    __syncthreads();
    int nl = t >> 2, fg = t & 3;
    int node = blockIdx.x * 64 + nl;
    if (node >= NN) return;
    float4 acc = make_float4(0.f, 0.f, 0.f, 0.f);
    #pragma unroll
    for (int kc = 0; kc < 32; ++kc) {
        float4 xv = shx[nl * 33 + kc];
        float4 w0 = shw[(kc * 4 + 0) * 4 + fg];
        float4 w1 = shw[(kc * 4 + 1) * 4 + fg];
        float4 w2 = shw[(kc * 4 + 2) * 4 + fg];
        float4 w3 = shw[(kc * 4 + 3) * 4 + fg];
        acc.x = fmaf(xv.x, w0.x, acc.x); acc.y = fmaf(xv.x, w0.y, acc.y);
        acc.z = fmaf(xv.x, w0.z, acc.z); acc.w = fmaf(xv.x, w0.w, acc.w);
        acc.x = fmaf(xv.y, w1.x, acc.x); acc.y = fmaf(xv.y, w1.y, acc.y);
        acc.z = fmaf(xv.y, w1.z, acc.z); acc.w = fmaf(xv.y, w1.w, acc.w);
        acc.x = fmaf(xv.z, w2.x, acc.x); acc.y = fmaf(xv.z, w2.y, acc.y);
        acc.z = fmaf(xv.z, w2.z, acc.z); acc.w = fmaf(xv.z, w2.w, acc.w);
        acc.x = fmaf(xv.w, w3.x, acc.x); acc.y = fmaf(xv.w, w3.y, acc.y);
        acc.z = fmaf(xv.w, w3.z, acc.z); acc.w = fmaf(xv.w, w3.w, acc.w);
    }
    float dv = g_dinv[node];
    __half2 h01 = __floats2half2_rn(acc.x * dv, acc.y * dv);
    __half2 h23 = __floats2half2_rn(acc.z * dv, acc.w * dv);
    uint2 pk;
    pk.x = *(unsigned int*)&h01;
    pk.y = *(unsigned int*)&h23;
    ((uint2*)g_h16a)[node * 4 + fg] = pk;
}

// Atomic-free aggregation, half-warp per dst, lane = feature, int4 csr loads.
// PHASE 1: out = fp16( relu(dinv*sum + b1) * dinv ) -> g_h16b
// PHASE 2: out = fp32 sum -> g_acc
template <int PHASE>
__global__ void agg_kernel(const float* __restrict__ b1) {
    int tid = blockIdx.x * blockDim.x + threadIdx.x;
    int dst = tid >> 4;
    int f   = tid & 15;
    if (dst >= NN) return;
    const __half* __restrict__ src = (PHASE == 1) ? g_h16a : g_h16b;
    float acc = __half2float(src[dst * CHID + f]);          // self-loop term
    int j   = g_offs[dst];
    int end = g_offs[dst + 1];
    for (; j < end; j += 4) {
        int4 s = *(const int4*)&g_csr[j];
        float a0 = __half2float(__ldg(&src[s.x * CHID + f]));
        float a1 = __half2float(__ldg(&src[s.y * CHID + f]));
        float a2 = __half2float(__ldg(&src[s.z * CHID + f]));
        float a3 = __half2float(__ldg(&src[s.w * CHID + f]));
        acc += (a0 + a1) + (a2 + a3);
    }
    if (PHASE == 1) {
        float dv = g_dinv[dst];
        float r  = fmaxf(fmaf(acc, dv, b1[f]), 0.f) * dv;
        g_h16b[dst * CHID + f] = __float2half(r);
    } else {
        g_acc[dst * CHID + f] = acc;
    }
}

// out[n,f] = b2[f] + dinv[n] * (acc2[n,:] @ W2[:,f])
// block: 64 nodes; 256 threads = 32 fgroups x 8 node-lanes; W2 in registers.
__global__ __launch_bounds__(256) void gemm2_kernel(const float4* __restrict__ W24,
                                                    const float4* __restrict__ b24,
                                                    float4* __restrict__ out4) {
    __shared__ float4 sht[64 * 5];      // 16 floats/row padded to 20
    int t = threadIdx.x;
    int node0 = blockIdx.x * 64;
    {
        int row = t >> 2, col = t & 3;
        if (node0 + row < NN)
            sht[row * 5 + col] = ((const float4*)g_acc)[node0 * 4 + t];
    }
    int fg = t & 31, nl = t >> 5;
    float4 w[16];
    #pragma unroll
    for (int k = 0; k < 16; ++k) w[k] = W24[k * 32 + fg];
    float4 bb = b24[fg];
    __syncthreads();
    #pragma unroll
    for (int it = 0; it < 8; ++it) {
        int ln = it * 8 + nl;
        int node = node0 + ln;
        if (node >= NN) return;
        float4 t0 = sht[ln * 5 + 0];
        float4 t1 = sht[ln * 5 + 1];
        float4 t2 = sht[ln * 5 + 2];
        float4 t3 = sht[ln * 5 + 3];
        float4 a = make_float4(0.f, 0.f, 0.f, 0.f);
        #define FMA4(val, wk) { a.x = fmaf(val, wk.x, a.x); a.y = fmaf(val, wk.y, a.y); \
                                a.z = fmaf(val, wk.z, a.z); a.w = fmaf(val, wk.w, a.w); }
        FMA4(t0.x, w[0])  FMA4(t0.y, w[1])  FMA4(t0.z, w[2])  FMA4(t0.w, w[3])
        FMA4(t1.x, w[4])  FMA4(t1.y, w[5])  FMA4(t1.z, w[6])  FMA4(t1.w, w[7])
        FMA4(t2.x, w[8])  FMA4(t2.y, w[9])  FMA4(t2.z, w[10]) FMA4(t2.w, w[11])
        FMA4(t3.x, w[12]) FMA4(t3.y, w[13]) FMA4(t3.z, w[14]) FMA4(t3.w, w[15])
        #undef FMA4
        float dv = g_dinv[node];
        float4 o;
        o.x = fmaf(a.x, dv, bb.x);
        o.y = fmaf(a.y, dv, bb.y);
        o.z = fmaf(a.z, dv, bb.z);
        o.w = fmaf(a.w, dv, bb.w);
        out4[(size_t)node * 32 + fg] = o;
    }
}

// ---------------- launch ----------------
extern "C" void kernel_launch(void* const* d_in, const int* in_sizes, int n_in,
                              void* d_out, int out_size) {
    const float* x    = (const float*)d_in[0];
    const void*  eidx = d_in[1];
    const float* W1   = (const float*)d_in[2];
    const float* b1   = (const float*)d_in[3];
    const float* W2   = (const float*)d_in[4];
    const float* b2   = (const float*)d_in[5];
    float*       out  = (float*)d_out;
    int E = in_sizes[1] / 2;

    init_kernel<<<(PADMAX / 4 + 255) / 256, 256>>>((const unsigned int*)eidx);
    prep_kernel<<<(E + 255) / 256, 256>>>(eidx, E);
    scanA_kernel<<<NB, SCAN_B>>>();
    scanB_kernel<<<1, 256>>>();
    scanC_kernel<<<(NN + 255) / 256, 256>>>();
    fill_kernel<<<(E + 255) / 256, 256>>>(E);

    gemm1_kernel<<<(NN + 63) / 64, 256>>>((const float4*)x, (const float4*)W1);
    agg_kernel<1><<<(NN * 16 + 255) / 256, 256>>>(b1);
    agg_kernel<2><<<(NN * 16 + 255) / 256, 256>>>(b1);
    gemm2_kernel<<<(NN + 63) / 64, 256>>>((const float4*)W2, (const float4*)b2,
                                          (float4*)out);
}